// round 1
// baseline (speedup 1.0000x reference)
#include <cuda_runtime.h>
#include <cuda_bf16.h>
#include <stdint.h>

#define N_RAYS   4096
#define N_INTERS 1536
#define NSAMP    1535          // N_INTERS - 1
#define RESV     128
#define CHAN     28
#define CHSTRIDE (128*128*128) // per-channel stride in data

__device__ int g_ray_count[N_RAYS];
__device__ int g_ray_base[N_RAYS];

// --- mask-critical math: must be bit-stable under --use_fast_math ---
__device__ __forceinline__ float voxel_len() {
    // float32( float32_sqrt(27) / 1536 )  == python float(np.linalg.norm(f32 [3,3,3]) / 1536)
    return __fdiv_rn(__fsqrt_rn(27.0f), 1536.0f);
}

__device__ __forceinline__ float compute_start(float ox, float oy, float oz,
                                               float dx, float dy, float dz) {
    float px = __fdiv_rn(1.5f - ox, dx);
    float py = __fdiv_rn(1.5f - oy, dy);
    float pz = __fdiv_rn(1.5f - oz, dz);
    float nx = __fdiv_rn(-1.5f - ox, dx);
    float ny = __fdiv_rn(-1.5f - oy, dy);
    float nz = __fdiv_rn(-1.5f - oz, dz);
    float ix = fminf(px, nx);
    float iy = fminf(py, ny);
    float iz = fminf(pz, nz);
    float s  = fmaxf(fmaxf(ix, iy), iz);
    return fminf(fmaxf(s, 0.2f), 6.0f);
}

__device__ __forceinline__ float sample_t(float start, int j) {
    return __fadd_rn(start, __fmul_rn((float)j, voxel_len()));
}

__device__ __forceinline__ void point_at(float start, int j,
                                         float ox, float oy, float oz,
                                         float dx, float dy, float dz,
                                         float& px, float& py, float& pz) {
    float t = sample_t(start, j);
    px = __fadd_rn(ox, __fmul_rn(t, dx));
    py = __fadd_rn(oy, __fmul_rn(t, dy));
    pz = __fadd_rn(oz, __fmul_rn(t, dz));
}

__device__ __forceinline__ bool in_box(float px, float py, float pz) {
    return (-1.5f < px) & (px < 1.5f) &
           (-1.5f < py) & (py < 1.5f) &
           (-1.5f < pz) & (pz < 1.5f);
}

// =====================  Kernel 1: intersections + mask + per-ray count ==============
__global__ void __launch_bounds__(256)
k_mask_count(const float* __restrict__ rays_o, const float* __restrict__ rays_d,
             float* __restrict__ mask_out, float* __restrict__ intr_out) {
    int ray = blockIdx.x;
    int tid = threadIdx.x;
    float ox = rays_o[ray*3+0], oy = rays_o[ray*3+1], oz = rays_o[ray*3+2];
    float dx = rays_d[ray*3+0], dy = rays_d[ray*3+1], dz = rays_d[ray*3+2];
    float start = compute_start(ox, oy, oz, dx, dy, dz);

    // full intersections (1536 values)
    for (int j = tid; j < N_INTERS; j += 256)
        intr_out[(size_t)ray * N_INTERS + j] = sample_t(start, j);

    int cnt = 0;
    for (int j = tid; j < NSAMP; j += 256) {
        float px, py, pz;
        point_at(start, j, ox, oy, oz, dx, dy, dz, px, py, pz);
        bool m = in_box(px, py, pz);
        mask_out[(size_t)ray * NSAMP + j] = m ? 1.0f : 0.0f;
        cnt += m;
    }
    // block reduce
    __shared__ int sh[8];
    for (int o = 16; o > 0; o >>= 1) cnt += __shfl_down_sync(0xffffffffu, cnt, o);
    if ((tid & 31) == 0) sh[tid >> 5] = cnt;
    __syncthreads();
    if (tid == 0) {
        int s = 0;
        #pragma unroll
        for (int w = 0; w < 8; w++) s += sh[w];
        g_ray_count[ray] = s;
    }
}

// =====================  Kernel 2: exclusive scan over 4096 ray counts ================
__global__ void __launch_bounds__(1024)
k_scan() {
    __shared__ int sh[1024];
    int tid = threadIdx.x;
    int c0 = g_ray_count[tid*4+0];
    int c1 = g_ray_count[tid*4+1];
    int c2 = g_ray_count[tid*4+2];
    int c3 = g_ray_count[tid*4+3];
    int tot = c0 + c1 + c2 + c3;
    sh[tid] = tot;
    __syncthreads();
    for (int off = 1; off < 1024; off <<= 1) {
        int v = (tid >= off) ? sh[tid - off] : 0;
        __syncthreads();
        sh[tid] += v;
        __syncthreads();
    }
    int excl = sh[tid] - tot;
    g_ray_base[tid*4+0] = excl;
    g_ray_base[tid*4+1] = excl + c0;
    g_ray_base[tid*4+2] = excl + c0 + c1;
    g_ray_base[tid*4+3] = excl + c0 + c1 + c2;
}

// =====================  Kernel 3: compaction + trilinear + sub_pts ===================
__global__ void __launch_bounds__(256)
k_gather(const float* __restrict__ rays_o, const float* __restrict__ rays_d,
         const float* __restrict__ data,
         float* __restrict__ data_out, float* __restrict__ sub_out) {
    int ray = blockIdx.x;
    int tid = threadIdx.x;
    int lane = tid & 31;
    int wid  = tid >> 5;
    float ox = rays_o[ray*3+0], oy = rays_o[ray*3+1], oz = rays_o[ray*3+2];
    float dx = rays_d[ray*3+0], dy = rays_d[ray*3+1], dz = rays_d[ray*3+2];
    float start = compute_start(ox, oy, oz, dx, dy, dz);
    int base = g_ray_base[ray];

    const float INV = __fdiv_rn(2.0f, 3.0f);

    __shared__ int sh_w[8];
    int chunk_base = 0;

    for (int cs = 0; cs < NSAMP; cs += 256) {
        int j = cs + tid;
        bool m = false;
        float px = 0.f, py = 0.f, pz = 0.f;
        if (j < NSAMP) {
            point_at(start, j, ox, oy, oz, dx, dy, dz, px, py, pz);
            m = in_box(px, py, pz);
        }
        unsigned b = __ballot_sync(0xffffffffu, m);
        int local = __popc(b & ((1u << lane) - 1u));
        if (lane == 0) sh_w[wid] = __popc(b);
        __syncthreads();
        int pre = 0, tot = 0;
        #pragma unroll
        for (int w = 0; w < 8; w++) {
            int v = sh_w[w];
            pre += (w < wid) ? v : 0;
            tot += v;
        }
        if (m) {
            int oidx = base + chunk_base + pre + local;

            // normalized coords (tolerant path — plain fp ok)
            float nx = (px + 1.5f) * INV - 1.0f;
            float ny = (py + 1.5f) * INV - 1.0f;
            float nz = (pz + 1.5f) * INV - 1.0f;

            // sub_pts: grid_pts = (norm+1)*64; idx = clip(floor,0,127); sub = gp - idx
            float gx = (nx + 1.0f) * 64.0f;
            float gy = (ny + 1.0f) * 64.0f;
            float gz = (nz + 1.0f) * 64.0f;
            float gix = fminf(fmaxf(floorf(gx), 0.0f), 127.0f);
            float giy = fminf(fmaxf(floorf(gy), 0.0f), 127.0f);
            float giz = fminf(fmaxf(floorf(gz), 0.0f), 127.0f);
            sub_out[(size_t)oidx*3+0] = gx - gix;
            sub_out[(size_t)oidx*3+1] = gy - giy;
            sub_out[(size_t)oidx*3+2] = gz - giz;

            // trilinear sample coords: x = (norm+1)*0.5*(W-1)
            float x = (nx + 1.0f) * 0.5f * 127.0f;
            float y = (ny + 1.0f) * 0.5f * 127.0f;
            float z = (nz + 1.0f) * 0.5f * 127.0f;
            float x0f = floorf(x), y0f = floorf(y), z0f = floorf(z);
            float fx = x - x0f, fy = y - y0f, fz = z - z0f;
            int ix0 = min(max((int)x0f, 0), 127);
            int iy0 = min(max((int)y0f, 0), 127);
            int iz0 = min(max((int)z0f, 0), 127);
            int ix1 = min(ix0 + 1, 127);
            int iy1 = min(iy0 + 1, 127);
            int iz1 = min(iz0 + 1, 127);

            float gxc = 1.0f - fx, gyc = 1.0f - fy, gzc = 1.0f - fz;
            float w000 = gzc * gyc * gxc;
            float w001 = gzc * gyc * fx;
            float w010 = gzc * fy  * gxc;
            float w011 = gzc * fy  * fx;
            float w100 = fz  * gyc * gxc;
            float w101 = fz  * gyc * fx;
            float w110 = fz  * fy  * gxc;
            float w111 = fz  * fy  * fx;

            int o000 = (iz0 * RESV + iy0) * RESV + ix0;
            int o001 = (iz0 * RESV + iy0) * RESV + ix1;
            int o010 = (iz0 * RESV + iy1) * RESV + ix0;
            int o011 = (iz0 * RESV + iy1) * RESV + ix1;
            int o100 = (iz1 * RESV + iy0) * RESV + ix0;
            int o101 = (iz1 * RESV + iy0) * RESV + ix1;
            int o110 = (iz1 * RESV + iy1) * RESV + ix0;
            int o111 = (iz1 * RESV + iy1) * RESV + ix1;

            float* op = data_out + (size_t)oidx * CHAN;
            #pragma unroll
            for (int c = 0; c < CHAN; c++) {
                const float* dc = data + (size_t)c * CHSTRIDE;
                float v = w000 * __ldg(dc + o000)
                        + w001 * __ldg(dc + o001)
                        + w010 * __ldg(dc + o010)
                        + w011 * __ldg(dc + o011)
                        + w100 * __ldg(dc + o100)
                        + w101 * __ldg(dc + o101)
                        + w110 * __ldg(dc + o110)
                        + w111 * __ldg(dc + o111);
                op[c] = v;
            }
        }
        chunk_base += tot;
        __syncthreads();  // protect sh_w reuse next chunk
    }
}

extern "C" void kernel_launch(void* const* d_in, const int* in_sizes, int n_in,
                              void* d_out, int out_size) {
    const float* rays_o = (const float*)d_in[0];
    const float* rays_d = (const float*)d_in[1];
    const float* data   = (const float*)d_in[2];
    float* out = (float*)d_out;

    // out layout: data_out [nm,28] | mask [4096,1535] | intersections [4096,1536] | sub_pts [nm,3]
    const long long MASK_N = (long long)N_RAYS * NSAMP;    // 6,287,360
    const long long INTR_N = (long long)N_RAYS * N_INTERS; // 6,291,456
    long long nm = ((long long)out_size - MASK_N - INTR_N) / 31LL;

    float* data_out = out;
    float* mask_out = out + nm * CHAN;
    float* intr_out = mask_out + MASK_N;
    float* sub_out  = intr_out + INTR_N;

    k_mask_count<<<N_RAYS, 256>>>(rays_o, rays_d, mask_out, intr_out);
    k_scan<<<1, 1024>>>();
    k_gather<<<N_RAYS, 256>>>(rays_o, rays_d, data, data_out, sub_out);
}

// round 2
// speedup vs baseline: 2.0902x; 2.0902x over previous
#include <cuda_runtime.h>
#include <cuda_bf16.h>
#include <stdint.h>

#define N_RAYS   4096
#define N_INTERS 1536
#define NSAMP    1535          // N_INTERS - 1
#define RESV     128
#define CHAN     28
#define NVOX     (128*128*128)
#define CHSTRIDE NVOX

__device__ int g_ray_count[N_RAYS];
__device__ int g_ray_base[N_RAYS];
// channel-last copy of the grid: voxel v -> 28 contiguous floats (112B, 16B-aligned)
__device__ float4 g_dataT4[(size_t)NVOX * 7];

// --- mask-critical math: must be bit-stable under --use_fast_math ---
__device__ __forceinline__ float voxel_len() {
    return __fdiv_rn(__fsqrt_rn(27.0f), 1536.0f);
}

__device__ __forceinline__ float compute_start(float ox, float oy, float oz,
                                               float dx, float dy, float dz) {
    float px = __fdiv_rn(1.5f - ox, dx);
    float py = __fdiv_rn(1.5f - oy, dy);
    float pz = __fdiv_rn(1.5f - oz, dz);
    float nx = __fdiv_rn(-1.5f - ox, dx);
    float ny = __fdiv_rn(-1.5f - oy, dy);
    float nz = __fdiv_rn(-1.5f - oz, dz);
    float ix = fminf(px, nx);
    float iy = fminf(py, ny);
    float iz = fminf(pz, nz);
    float s  = fmaxf(fmaxf(ix, iy), iz);
    return fminf(fmaxf(s, 0.2f), 6.0f);
}

__device__ __forceinline__ float sample_t(float start, int j) {
    return __fadd_rn(start, __fmul_rn((float)j, voxel_len()));
}

__device__ __forceinline__ void point_at(float start, int j,
                                         float ox, float oy, float oz,
                                         float dx, float dy, float dz,
                                         float& px, float& py, float& pz) {
    float t = sample_t(start, j);
    px = __fadd_rn(ox, __fmul_rn(t, dx));
    py = __fadd_rn(oy, __fmul_rn(t, dy));
    pz = __fadd_rn(oz, __fmul_rn(t, dz));
}

__device__ __forceinline__ bool in_box(float px, float py, float pz) {
    return (-1.5f < px) & (px < 1.5f) &
           (-1.5f < py) & (py < 1.5f) &
           (-1.5f < pz) & (pz < 1.5f);
}

// =====================  Kernel 0: transpose [28, V] -> [V, 28]  ======================
__global__ void __launch_bounds__(896)
k_transpose(const float* __restrict__ data) {
    __shared__ float tile[2][28][33];
    float* gT = (float*)g_dataT4;
    int x = threadIdx.x & 31;          // voxel lane within tile
    int y = threadIdx.x >> 5;          // channel (warp id), 0..27
    int t = threadIdx.x;
    int row = t % 28, col = t / 28;    // transposed read coords

    #pragma unroll
    for (int it = 0; it < 8; it++) {
        int v0 = blockIdx.x * 256 + it * 32;
        int buf = it & 1;
        tile[buf][y][x] = __ldg(data + (size_t)y * CHSTRIDE + v0 + x);
        __syncthreads();
        gT[(size_t)v0 * CHAN + t] = tile[buf][row][col];
    }
}

// =====================  Kernel 1: intersections + mask + per-ray count ==============
__global__ void __launch_bounds__(256)
k_mask_count(const float* __restrict__ rays_o, const float* __restrict__ rays_d,
             float* __restrict__ mask_out, float* __restrict__ intr_out) {
    int ray = blockIdx.x;
    int tid = threadIdx.x;
    float ox = rays_o[ray*3+0], oy = rays_o[ray*3+1], oz = rays_o[ray*3+2];
    float dx = rays_d[ray*3+0], dy = rays_d[ray*3+1], dz = rays_d[ray*3+2];
    float start = compute_start(ox, oy, oz, dx, dy, dz);

    for (int j = tid; j < N_INTERS; j += 256)
        __stcs(intr_out + (size_t)ray * N_INTERS + j, sample_t(start, j));

    int cnt = 0;
    for (int j = tid; j < NSAMP; j += 256) {
        float px, py, pz;
        point_at(start, j, ox, oy, oz, dx, dy, dz, px, py, pz);
        bool m = in_box(px, py, pz);
        __stcs(mask_out + (size_t)ray * NSAMP + j, m ? 1.0f : 0.0f);
        cnt += m;
    }
    __shared__ int sh[8];
    for (int o = 16; o > 0; o >>= 1) cnt += __shfl_down_sync(0xffffffffu, cnt, o);
    if ((tid & 31) == 0) sh[tid >> 5] = cnt;
    __syncthreads();
    if (tid == 0) {
        int s = 0;
        #pragma unroll
        for (int w = 0; w < 8; w++) s += sh[w];
        g_ray_count[ray] = s;
    }
}

// =====================  Kernel 2: exclusive scan over 4096 ray counts ================
__global__ void __launch_bounds__(1024)
k_scan() {
    __shared__ int sh[1024];
    int tid = threadIdx.x;
    int c0 = g_ray_count[tid*4+0];
    int c1 = g_ray_count[tid*4+1];
    int c2 = g_ray_count[tid*4+2];
    int c3 = g_ray_count[tid*4+3];
    int tot = c0 + c1 + c2 + c3;
    sh[tid] = tot;
    __syncthreads();
    for (int off = 1; off < 1024; off <<= 1) {
        int v = (tid >= off) ? sh[tid - off] : 0;
        __syncthreads();
        sh[tid] += v;
        __syncthreads();
    }
    int excl = sh[tid] - tot;
    g_ray_base[tid*4+0] = excl;
    g_ray_base[tid*4+1] = excl + c0;
    g_ray_base[tid*4+2] = excl + c0 + c1;
    g_ray_base[tid*4+3] = excl + c0 + c1 + c2;
}

// =====================  Kernel 3: gather (mask is a j-prefix: no compaction logic) ===
__global__ void __launch_bounds__(256)
k_gather(const float* __restrict__ rays_o, const float* __restrict__ rays_d,
         float* __restrict__ data_out, float* __restrict__ sub_out) {
    int ray = blockIdx.x;
    int tid = threadIdx.x;
    float ox = rays_o[ray*3+0], oy = rays_o[ray*3+1], oz = rays_o[ray*3+2];
    float dx = rays_d[ray*3+0], dy = rays_d[ray*3+1], dz = rays_d[ray*3+2];
    float start = compute_start(ox, oy, oz, dx, dy, dz);
    int cnt  = g_ray_count[ray];
    int base = g_ray_base[ray];

    const float INV = __fdiv_rn(2.0f, 3.0f);

    for (int j = tid; j < cnt; j += 256) {
        float px, py, pz;
        point_at(start, j, ox, oy, oz, dx, dy, dz, px, py, pz);
        int oidx = base + j;

        // normalized coords (tolerant path)
        float nx = (px + 1.5f) * INV - 1.0f;
        float ny = (py + 1.5f) * INV - 1.0f;
        float nz = (pz + 1.5f) * INV - 1.0f;

        // sub_pts
        float gx = (nx + 1.0f) * 64.0f;
        float gy = (ny + 1.0f) * 64.0f;
        float gz = (nz + 1.0f) * 64.0f;
        float gix = fminf(fmaxf(floorf(gx), 0.0f), 127.0f);
        float giy = fminf(fmaxf(floorf(gy), 0.0f), 127.0f);
        float giz = fminf(fmaxf(floorf(gz), 0.0f), 127.0f);
        __stcs(sub_out + (size_t)oidx*3+0, gx - gix);
        __stcs(sub_out + (size_t)oidx*3+1, gy - giy);
        __stcs(sub_out + (size_t)oidx*3+2, gz - giz);

        // trilinear coords
        float x = (nx + 1.0f) * 0.5f * 127.0f;
        float y = (ny + 1.0f) * 0.5f * 127.0f;
        float z = (nz + 1.0f) * 0.5f * 127.0f;
        float x0f = floorf(x), y0f = floorf(y), z0f = floorf(z);
        float fx = x - x0f, fy = y - y0f, fz = z - z0f;
        int ix0 = min(max((int)x0f, 0), 127);
        int iy0 = min(max((int)y0f, 0), 127);
        int iz0 = min(max((int)z0f, 0), 127);
        int ix1 = min(ix0 + 1, 127);
        int iy1 = min(iy0 + 1, 127);
        int iz1 = min(iz0 + 1, 127);

        float gxc = 1.0f - fx, gyc = 1.0f - fy, gzc = 1.0f - fz;
        float w000 = gzc * gyc * gxc;
        float w001 = gzc * gyc * fx;
        float w010 = gzc * fy  * gxc;
        float w011 = gzc * fy  * fx;
        float w100 = fz  * gyc * gxc;
        float w101 = fz  * gyc * fx;
        float w110 = fz  * fy  * gxc;
        float w111 = fz  * fy  * fx;

        size_t b00 = ((size_t)(iz0 * RESV + iy0) * RESV);
        size_t b01 = ((size_t)(iz0 * RESV + iy1) * RESV);
        size_t b10 = ((size_t)(iz1 * RESV + iy0) * RESV);
        size_t b11 = ((size_t)(iz1 * RESV + iy1) * RESV);

        const float4* p000 = g_dataT4 + (b00 + ix0) * 7;
        const float4* p001 = g_dataT4 + (b00 + ix1) * 7;
        const float4* p010 = g_dataT4 + (b01 + ix0) * 7;
        const float4* p011 = g_dataT4 + (b01 + ix1) * 7;
        const float4* p100 = g_dataT4 + (b10 + ix0) * 7;
        const float4* p101 = g_dataT4 + (b10 + ix1) * 7;
        const float4* p110 = g_dataT4 + (b11 + ix0) * 7;
        const float4* p111 = g_dataT4 + (b11 + ix1) * 7;

        float4* op = (float4*)(data_out + (size_t)oidx * CHAN);
        #pragma unroll
        for (int g = 0; g < 7; g++) {
            float4 a = __ldg(p000 + g);
            float4 b = __ldg(p001 + g);
            float4 c = __ldg(p010 + g);
            float4 d = __ldg(p011 + g);
            float4 e = __ldg(p100 + g);
            float4 f = __ldg(p101 + g);
            float4 h = __ldg(p110 + g);
            float4 i = __ldg(p111 + g);
            float4 r;
            r.x = w000*a.x + w001*b.x + w010*c.x + w011*d.x
                + w100*e.x + w101*f.x + w110*h.x + w111*i.x;
            r.y = w000*a.y + w001*b.y + w010*c.y + w011*d.y
                + w100*e.y + w101*f.y + w110*h.y + w111*i.y;
            r.z = w000*a.z + w001*b.z + w010*c.z + w011*d.z
                + w100*e.z + w101*f.z + w110*h.z + w111*i.z;
            r.w = w000*a.w + w001*b.w + w010*c.w + w011*d.w
                + w100*e.w + w101*f.w + w110*h.w + w111*i.w;
            __stcs(op + g, r);
        }
    }
}

extern "C" void kernel_launch(void* const* d_in, const int* in_sizes, int n_in,
                              void* d_out, int out_size) {
    const float* rays_o = (const float*)d_in[0];
    const float* rays_d = (const float*)d_in[1];
    const float* data   = (const float*)d_in[2];
    float* out = (float*)d_out;

    const long long MASK_N = (long long)N_RAYS * NSAMP;    // 6,287,360
    const long long INTR_N = (long long)N_RAYS * N_INTERS; // 6,291,456
    long long nm = ((long long)out_size - MASK_N - INTR_N) / 31LL;

    float* data_out = out;
    float* mask_out = out + nm * CHAN;
    float* intr_out = mask_out + MASK_N;
    float* sub_out  = intr_out + INTR_N;

    k_transpose<<<NVOX / 256, 896>>>(data);
    k_mask_count<<<N_RAYS, 256>>>(rays_o, rays_d, mask_out, intr_out);
    k_scan<<<1, 1024>>>();
    k_gather<<<N_RAYS, 256>>>(rays_o, rays_d, data_out, sub_out);
}

// round 3
// speedup vs baseline: 2.2691x; 1.0856x over previous
#include <cuda_runtime.h>
#include <cuda_bf16.h>
#include <stdint.h>

#define N_RAYS   4096
#define N_INTERS 1536
#define NSAMP    1535          // N_INTERS - 1
#define RESV     128
#define CHAN     28
#define NVOX     (128*128*128)
#define CHSTRIDE NVOX

__device__ int    g_ray_count[N_RAYS];
__device__ int    g_ray_base[N_RAYS];
__device__ int    g_map[(size_t)N_RAYS * NSAMP];   // oidx -> (ray<<11)|j
struct RayPack { float4 o_start; float4 d; };
__device__ RayPack g_raypack[N_RAYS];
// channel-last copy of the grid: voxel v -> 28 contiguous floats (112B, 16B-aligned)
__device__ float4 g_dataT4[(size_t)NVOX * 7];

// --- mask-critical math: must be bit-stable under --use_fast_math ---
__device__ __forceinline__ float voxel_len() {
    return __fdiv_rn(__fsqrt_rn(27.0f), 1536.0f);
}

__device__ __forceinline__ float compute_start(float ox, float oy, float oz,
                                               float dx, float dy, float dz) {
    float px = __fdiv_rn(1.5f - ox, dx);
    float py = __fdiv_rn(1.5f - oy, dy);
    float pz = __fdiv_rn(1.5f - oz, dz);
    float nx = __fdiv_rn(-1.5f - ox, dx);
    float ny = __fdiv_rn(-1.5f - oy, dy);
    float nz = __fdiv_rn(-1.5f - oz, dz);
    float ix = fminf(px, nx);
    float iy = fminf(py, ny);
    float iz = fminf(pz, nz);
    float s  = fmaxf(fmaxf(ix, iy), iz);
    return fminf(fmaxf(s, 0.2f), 6.0f);
}

__device__ __forceinline__ float sample_t(float start, int j) {
    return __fadd_rn(start, __fmul_rn((float)j, voxel_len()));
}

__device__ __forceinline__ void point_at(float start, int j,
                                         float ox, float oy, float oz,
                                         float dx, float dy, float dz,
                                         float& px, float& py, float& pz) {
    float t = sample_t(start, j);
    px = __fadd_rn(ox, __fmul_rn(t, dx));
    py = __fadd_rn(oy, __fmul_rn(t, dy));
    pz = __fadd_rn(oz, __fmul_rn(t, dz));
}

__device__ __forceinline__ bool in_box(float px, float py, float pz) {
    return (-1.5f < px) & (px < 1.5f) &
           (-1.5f < py) & (py < 1.5f) &
           (-1.5f < pz) & (pz < 1.5f);
}

// =====================  Kernel 0: transpose [28, V] -> [V, 28]  ======================
__global__ void __launch_bounds__(896)
k_transpose(const float* __restrict__ data) {
    __shared__ float tile[2][28][33];
    float* gT = (float*)g_dataT4;
    int x = threadIdx.x & 31;          // voxel lane within tile
    int y = threadIdx.x >> 5;          // channel (warp id), 0..27
    int t = threadIdx.x;
    int row = t % 28, col = t / 28;    // transposed read coords

    #pragma unroll
    for (int it = 0; it < 8; it++) {
        int v0 = blockIdx.x * 256 + it * 32;
        int buf = it & 1;
        tile[buf][y][x] = __ldg(data + (size_t)y * CHSTRIDE + v0 + x);
        __syncthreads();
        gT[(size_t)v0 * CHAN + t] = tile[buf][row][col];
    }
}

// =====================  Kernel 1: intersections + mask + count + raypack ============
__global__ void __launch_bounds__(256)
k_mask_count(const float* __restrict__ rays_o, const float* __restrict__ rays_d,
             float* __restrict__ mask_out, float* __restrict__ intr_out) {
    int ray = blockIdx.x;
    int tid = threadIdx.x;
    float ox = rays_o[ray*3+0], oy = rays_o[ray*3+1], oz = rays_o[ray*3+2];
    float dx = rays_d[ray*3+0], dy = rays_d[ray*3+1], dz = rays_d[ray*3+2];
    float start = compute_start(ox, oy, oz, dx, dy, dz);

    if (tid == 0) {
        RayPack rp;
        rp.o_start = make_float4(ox, oy, oz, start);
        rp.d       = make_float4(dx, dy, dz, 0.0f);
        g_raypack[ray] = rp;
    }

    for (int j = tid; j < N_INTERS; j += 256)
        __stcs(intr_out + (size_t)ray * N_INTERS + j, sample_t(start, j));

    int cnt = 0;
    for (int j = tid; j < NSAMP; j += 256) {
        float px, py, pz;
        point_at(start, j, ox, oy, oz, dx, dy, dz, px, py, pz);
        bool m = in_box(px, py, pz);
        __stcs(mask_out + (size_t)ray * NSAMP + j, m ? 1.0f : 0.0f);
        cnt += m;
    }
    __shared__ int sh[8];
    for (int o = 16; o > 0; o >>= 1) cnt += __shfl_down_sync(0xffffffffu, cnt, o);
    if ((tid & 31) == 0) sh[tid >> 5] = cnt;
    __syncthreads();
    if (tid == 0) {
        int s = 0;
        #pragma unroll
        for (int w = 0; w < 8; w++) s += sh[w];
        g_ray_count[ray] = s;
    }
}

// =====================  Kernel 2: exclusive scan over 4096 ray counts ================
__global__ void __launch_bounds__(1024)
k_scan() {
    __shared__ int sh[1024];
    int tid = threadIdx.x;
    int c0 = g_ray_count[tid*4+0];
    int c1 = g_ray_count[tid*4+1];
    int c2 = g_ray_count[tid*4+2];
    int c3 = g_ray_count[tid*4+3];
    int tot = c0 + c1 + c2 + c3;
    sh[tid] = tot;
    __syncthreads();
    for (int off = 1; off < 1024; off <<= 1) {
        int v = (tid >= off) ? sh[tid - off] : 0;
        __syncthreads();
        sh[tid] += v;
        __syncthreads();
    }
    int excl = sh[tid] - tot;
    g_ray_base[tid*4+0] = excl;
    g_ray_base[tid*4+1] = excl + c0;
    g_ray_base[tid*4+2] = excl + c0 + c1;
    g_ray_base[tid*4+3] = excl + c0 + c1 + c2;
}

// =====================  Kernel 2b: build oidx -> (ray, j) map  =======================
__global__ void __launch_bounds__(256)
k_build_map() {
    int ray  = blockIdx.x;
    int cnt  = g_ray_count[ray];
    int base = g_ray_base[ray];
    int tag  = ray << 11;
    for (int j = threadIdx.x; j < cnt; j += 256)
        g_map[base + j] = tag | j;
}

// =====================  Kernel 3: flat gather, 8 lanes per sample  ===================
__global__ void __launch_bounds__(256)
k_gather(float* __restrict__ data_out, float* __restrict__ sub_out, int nm) {
    int gt = blockIdx.x * 256 + threadIdx.x;
    int s   = gt >> 3;
    int sub = gt & 7;
    if (s >= nm) return;

    int info = __ldg(&g_map[s]);
    int ray = info >> 11;
    int j   = info & 2047;

    float4 osr = __ldg(&g_raypack[ray].o_start);
    float4 dd  = __ldg(&g_raypack[ray].d);

    float px, py, pz;
    point_at(osr.w, j, osr.x, osr.y, osr.z, dd.x, dd.y, dd.z, px, py, pz);

    // normalized coords (tolerant path)
    const float INV = 0.66666668653f;  // float(2/3)
    float nx = (px + 1.5f) * INV - 1.0f;
    float ny = (py + 1.5f) * INV - 1.0f;
    float nz = (pz + 1.5f) * INV - 1.0f;

    if (sub == 7) {
        // sub_pts lane
        float gx = (nx + 1.0f) * 64.0f;
        float gy = (ny + 1.0f) * 64.0f;
        float gz = (nz + 1.0f) * 64.0f;
        float gix = fminf(fmaxf(floorf(gx), 0.0f), 127.0f);
        float giy = fminf(fmaxf(floorf(gy), 0.0f), 127.0f);
        float giz = fminf(fmaxf(floorf(gz), 0.0f), 127.0f);
        __stcs(sub_out + (size_t)s*3+0, gx - gix);
        __stcs(sub_out + (size_t)s*3+1, gy - giy);
        __stcs(sub_out + (size_t)s*3+2, gz - giz);
        return;
    }

    // trilinear coords
    float x = (nx + 1.0f) * 63.5f;
    float y = (ny + 1.0f) * 63.5f;
    float z = (nz + 1.0f) * 63.5f;
    float x0f = floorf(x), y0f = floorf(y), z0f = floorf(z);
    float fx = x - x0f, fy = y - y0f, fz = z - z0f;
    int ix0 = min(max((int)x0f, 0), 127);
    int iy0 = min(max((int)y0f, 0), 127);
    int iz0 = min(max((int)z0f, 0), 127);
    int ix1 = min(ix0 + 1, 127);
    int iy1 = min(iy0 + 1, 127);
    int iz1 = min(iz0 + 1, 127);

    float gxc = 1.0f - fx, gyc = 1.0f - fy, gzc = 1.0f - fz;
    float w000 = gzc * gyc * gxc;
    float w001 = gzc * gyc * fx;
    float w010 = gzc * fy  * gxc;
    float w011 = gzc * fy  * fx;
    float w100 = fz  * gyc * gxc;
    float w101 = fz  * gyc * fx;
    float w110 = fz  * fy  * gxc;
    float w111 = fz  * fy  * fx;

    int b00 = (iz0 * RESV + iy0) * RESV;
    int b01 = (iz0 * RESV + iy1) * RESV;
    int b10 = (iz1 * RESV + iy0) * RESV;
    int b11 = (iz1 * RESV + iy1) * RESV;

    const float4* G = g_dataT4;
    float4 a = __ldg(G + (size_t)(b00 + ix0) * 7 + sub);
    float4 b = __ldg(G + (size_t)(b00 + ix1) * 7 + sub);
    float4 c = __ldg(G + (size_t)(b01 + ix0) * 7 + sub);
    float4 d = __ldg(G + (size_t)(b01 + ix1) * 7 + sub);
    float4 e = __ldg(G + (size_t)(b10 + ix0) * 7 + sub);
    float4 f = __ldg(G + (size_t)(b10 + ix1) * 7 + sub);
    float4 h = __ldg(G + (size_t)(b11 + ix0) * 7 + sub);
    float4 i = __ldg(G + (size_t)(b11 + ix1) * 7 + sub);

    float4 r;
    r.x = w000*a.x + w001*b.x + w010*c.x + w011*d.x
        + w100*e.x + w101*f.x + w110*h.x + w111*i.x;
    r.y = w000*a.y + w001*b.y + w010*c.y + w011*d.y
        + w100*e.y + w101*f.y + w110*h.y + w111*i.y;
    r.z = w000*a.z + w001*b.z + w010*c.z + w011*d.z
        + w100*e.z + w101*f.z + w110*h.z + w111*i.z;
    r.w = w000*a.w + w001*b.w + w010*c.w + w011*d.w
        + w100*e.w + w101*f.w + w110*h.w + w111*i.w;

    __stcs((float4*)(data_out + (size_t)s * CHAN) + sub, r);
}

extern "C" void kernel_launch(void* const* d_in, const int* in_sizes, int n_in,
                              void* d_out, int out_size) {
    const float* rays_o = (const float*)d_in[0];
    const float* rays_d = (const float*)d_in[1];
    const float* data   = (const float*)d_in[2];
    float* out = (float*)d_out;

    const long long MASK_N = (long long)N_RAYS * NSAMP;    // 6,287,360
    const long long INTR_N = (long long)N_RAYS * N_INTERS; // 6,291,456
    long long nm = ((long long)out_size - MASK_N - INTR_N) / 31LL;

    float* data_out = out;
    float* mask_out = out + nm * CHAN;
    float* intr_out = mask_out + MASK_N;
    float* sub_out  = intr_out + INTR_N;

    k_transpose<<<NVOX / 256, 896>>>(data);
    k_mask_count<<<N_RAYS, 256>>>(rays_o, rays_d, mask_out, intr_out);
    k_scan<<<1, 1024>>>();
    k_build_map<<<N_RAYS, 256>>>();

    long long nthreads = nm * 8;
    int nblocks = (int)((nthreads + 255) / 256);
    k_gather<<<nblocks, 256>>>(data_out, sub_out, (int)nm);
}

// round 5
// speedup vs baseline: 2.6737x; 1.1783x over previous
#include <cuda_runtime.h>
#include <cuda_fp16.h>
#include <cuda_bf16.h>
#include <stdint.h>

#define N_RAYS   4096
#define N_INTERS 1536
#define NSAMP    1535          // N_INTERS - 1
#define RESV     128
#define CHAN     28
#define NVOX     (128*128*128)
#define CHSTRIDE NVOX
#define TR_BLOCKS (NVOX / 256)   // 8192 transpose blocks

__device__ int    g_ray_count[N_RAYS];
__device__ int    g_ray_base[N_RAYS];
__device__ int    g_map[(size_t)N_RAYS * NSAMP];   // oidx -> (ray<<11)|j
struct RayPack { float4 o_start; float4 d; };
__device__ RayPack g_raypack[N_RAYS];

// channel-last fp16 grid: voxel record = 28 halves = 56B = 7x uint2 (8B each)
__device__ uint2 g_dataH[(size_t)NVOX * 7];

// --- mask-critical math: must be bit-stable under --use_fast_math ---
__device__ __forceinline__ float voxel_len() {
    return __fdiv_rn(__fsqrt_rn(27.0f), 1536.0f);
}

__device__ __forceinline__ float compute_start(float ox, float oy, float oz,
                                               float dx, float dy, float dz) {
    float px = __fdiv_rn(1.5f - ox, dx);
    float py = __fdiv_rn(1.5f - oy, dy);
    float pz = __fdiv_rn(1.5f - oz, dz);
    float nx = __fdiv_rn(-1.5f - ox, dx);
    float ny = __fdiv_rn(-1.5f - oy, dy);
    float nz = __fdiv_rn(-1.5f - oz, dz);
    float ix = fminf(px, nx);
    float iy = fminf(py, ny);
    float iz = fminf(pz, nz);
    float s  = fmaxf(fmaxf(ix, iy), iz);
    return fminf(fmaxf(s, 0.2f), 6.0f);
}

__device__ __forceinline__ float sample_t(float start, int j) {
    return __fadd_rn(start, __fmul_rn((float)j, voxel_len()));
}

__device__ __forceinline__ void point_at(float start, int j,
                                         float ox, float oy, float oz,
                                         float dx, float dy, float dz,
                                         float& px, float& py, float& pz) {
    float t = sample_t(start, j);
    px = __fadd_rn(ox, __fmul_rn(t, dx));
    py = __fadd_rn(oy, __fmul_rn(t, dy));
    pz = __fadd_rn(oz, __fmul_rn(t, dz));
}

__device__ __forceinline__ bool in_box(float px, float py, float pz) {
    return (-1.5f < px) & (px < 1.5f) &
           (-1.5f < py) & (py < 1.5f) &
           (-1.5f < pz) & (pz < 1.5f);
}

// unpack a uint2 (4 halves) into two float2
__device__ __forceinline__ void unpack4(uint2 u, float2& lo, float2& hi) {
    __half2 h0 = *reinterpret_cast<__half2*>(&u.x);
    __half2 h1 = *reinterpret_cast<__half2*>(&u.y);
    lo = __half22float2(h0);
    hi = __half22float2(h1);
}

// ============ Kernel 0 (fused): transpose->fp16  +  mask/count/intersections ========
__global__ void __launch_bounds__(256)
k_pre(const float* __restrict__ data,
      const float* __restrict__ rays_o, const float* __restrict__ rays_d,
      float* __restrict__ mask_out, float* __restrict__ intr_out) {
    __shared__ float tile[28][257];
    int tid = threadIdx.x;

    if (blockIdx.x < TR_BLOCKS) {
        // -------- transpose path: 256 voxels per block --------
        int v0 = blockIdx.x * 256;
        #pragma unroll
        for (int c = 0; c < 28; c++)
            tile[c][tid] = __ldg(data + (size_t)c * CHSTRIDE + v0 + tid);
        __syncthreads();
        unsigned* out = (unsigned*)g_dataH;
        #pragma unroll
        for (int k = 0; k < 14; k++) {
            int l  = k * 256 + tid;      // [0, 3584)
            int v  = l / 14;
            int c2 = l - v * 14;         // half2 pair index
            __half2 h = __floats2half2_rn(tile[2*c2][v], tile[2*c2+1][v]);
            out[(size_t)(v0 + v) * 14 + c2] = *reinterpret_cast<unsigned*>(&h);
        }
        return;
    }

    // -------- mask path --------
    int ray = blockIdx.x - TR_BLOCKS;
    float ox = rays_o[ray*3+0], oy = rays_o[ray*3+1], oz = rays_o[ray*3+2];
    float dx = rays_d[ray*3+0], dy = rays_d[ray*3+1], dz = rays_d[ray*3+2];
    float start = compute_start(ox, oy, oz, dx, dy, dz);

    if (tid == 0) {
        RayPack rp;
        rp.o_start = make_float4(ox, oy, oz, start);
        rp.d       = make_float4(dx, dy, dz, 0.0f);
        g_raypack[ray] = rp;
    }

    for (int j = tid; j < N_INTERS; j += 256)
        __stcs(intr_out + (size_t)ray * N_INTERS + j, sample_t(start, j));

    int cnt = 0;
    for (int j = tid; j < NSAMP; j += 256) {
        float px, py, pz;
        point_at(start, j, ox, oy, oz, dx, dy, dz, px, py, pz);
        bool m = in_box(px, py, pz);
        __stcs(mask_out + (size_t)ray * NSAMP + j, m ? 1.0f : 0.0f);
        cnt += m;
    }
    int* sh = (int*)tile;  // reuse smem
    for (int o = 16; o > 0; o >>= 1) cnt += __shfl_down_sync(0xffffffffu, cnt, o);
    if ((tid & 31) == 0) sh[tid >> 5] = cnt;
    __syncthreads();
    if (tid == 0) {
        int s = 0;
        #pragma unroll
        for (int w = 0; w < 8; w++) s += sh[w];
        g_ray_count[ray] = s;
    }
}

// =====================  Kernel 2: exclusive scan over 4096 ray counts ================
__global__ void __launch_bounds__(1024)
k_scan() {
    __shared__ int sh[1024];
    int tid = threadIdx.x;
    int c0 = g_ray_count[tid*4+0];
    int c1 = g_ray_count[tid*4+1];
    int c2 = g_ray_count[tid*4+2];
    int c3 = g_ray_count[tid*4+3];
    int tot = c0 + c1 + c2 + c3;
    sh[tid] = tot;
    __syncthreads();
    for (int off = 1; off < 1024; off <<= 1) {
        int v = (tid >= off) ? sh[tid - off] : 0;
        __syncthreads();
        sh[tid] += v;
        __syncthreads();
    }
    int excl = sh[tid] - tot;
    g_ray_base[tid*4+0] = excl;
    g_ray_base[tid*4+1] = excl + c0;
    g_ray_base[tid*4+2] = excl + c0 + c1;
    g_ray_base[tid*4+3] = excl + c0 + c1 + c2;
}

// =====================  Kernel 2b: build oidx -> (ray, j) map  =======================
__global__ void __launch_bounds__(256)
k_build_map() {
    int ray  = blockIdx.x;
    int cnt  = g_ray_count[ray];
    int base = g_ray_base[ray];
    int tag  = ray << 11;
    for (int j = threadIdx.x; j < cnt; j += 256)
        g_map[base + j] = tag | j;
}

// =====================  Kernel 3: flat gather, 8 lanes per sample, fp16 grid =========
__global__ void __launch_bounds__(256)
k_gather(float* __restrict__ data_out, float* __restrict__ sub_out, int nm) {
    int gt = blockIdx.x * 256 + threadIdx.x;
    int s   = gt >> 3;
    int sub = gt & 7;
    if (s >= nm) return;

    int info = __ldg(&g_map[s]);
    int ray = info >> 11;
    int j   = info & 2047;

    float4 osr = __ldg(&g_raypack[ray].o_start);
    float4 dd  = __ldg(&g_raypack[ray].d);

    float px, py, pz;
    point_at(osr.w, j, osr.x, osr.y, osr.z, dd.x, dd.y, dd.z, px, py, pz);

    const float INV = 0.66666668653f;  // float(2/3)
    float nx = (px + 1.5f) * INV - 1.0f;
    float ny = (py + 1.5f) * INV - 1.0f;
    float nz = (pz + 1.5f) * INV - 1.0f;

    if (sub == 7) {
        float gx = (nx + 1.0f) * 64.0f;
        float gy = (ny + 1.0f) * 64.0f;
        float gz = (nz + 1.0f) * 64.0f;
        float gix = fminf(fmaxf(floorf(gx), 0.0f), 127.0f);
        float giy = fminf(fmaxf(floorf(gy), 0.0f), 127.0f);
        float giz = fminf(fmaxf(floorf(gz), 0.0f), 127.0f);
        __stcs(sub_out + (size_t)s*3+0, gx - gix);
        __stcs(sub_out + (size_t)s*3+1, gy - giy);
        __stcs(sub_out + (size_t)s*3+2, gz - giz);
        return;
    }

    float x = (nx + 1.0f) * 63.5f;
    float y = (ny + 1.0f) * 63.5f;
    float z = (nz + 1.0f) * 63.5f;
    float x0f = floorf(x), y0f = floorf(y), z0f = floorf(z);
    float fx = x - x0f, fy = y - y0f, fz = z - z0f;
    int ix0 = min(max((int)x0f, 0), 127);
    int iy0 = min(max((int)y0f, 0), 127);
    int iz0 = min(max((int)z0f, 0), 127);
    int ix1 = min(ix0 + 1, 127);
    int iy1 = min(iy0 + 1, 127);
    int iz1 = min(iz0 + 1, 127);

    float gxc = 1.0f - fx, gyc = 1.0f - fy, gzc = 1.0f - fz;
    float w000 = gzc * gyc * gxc;
    float w001 = gzc * gyc * fx;
    float w010 = gzc * fy  * gxc;
    float w011 = gzc * fy  * fx;
    float w100 = fz  * gyc * gxc;
    float w101 = fz  * gyc * fx;
    float w110 = fz  * fy  * gxc;
    float w111 = fz  * fy  * fx;

    int b00 = (iz0 * RESV + iy0) * RESV;
    int b01 = (iz0 * RESV + iy1) * RESV;
    int b10 = (iz1 * RESV + iy0) * RESV;
    int b11 = (iz1 * RESV + iy1) * RESV;

    const uint2* G = g_dataH;
    uint2 a = __ldg(G + (size_t)(b00 + ix0) * 7 + sub);
    uint2 b = __ldg(G + (size_t)(b00 + ix1) * 7 + sub);
    uint2 c = __ldg(G + (size_t)(b01 + ix0) * 7 + sub);
    uint2 d = __ldg(G + (size_t)(b01 + ix1) * 7 + sub);
    uint2 e = __ldg(G + (size_t)(b10 + ix0) * 7 + sub);
    uint2 f = __ldg(G + (size_t)(b10 + ix1) * 7 + sub);
    uint2 h = __ldg(G + (size_t)(b11 + ix0) * 7 + sub);
    uint2 i = __ldg(G + (size_t)(b11 + ix1) * 7 + sub);

    float2 aL, aH, bL, bH, cL, cH, dL, dH, eL, eH, fL, fH, hL, hH, iL, iH;
    unpack4(a, aL, aH);
    unpack4(b, bL, bH);
    unpack4(c, cL, cH);
    unpack4(d, dL, dH);
    unpack4(e, eL, eH);
    unpack4(f, fL, fH);
    unpack4(h, hL, hH);
    unpack4(i, iL, iH);

    float4 r;
    r.x = w000*aL.x + w001*bL.x + w010*cL.x + w011*dL.x
        + w100*eL.x + w101*fL.x + w110*hL.x + w111*iL.x;
    r.y = w000*aL.y + w001*bL.y + w010*cL.y + w011*dL.y
        + w100*eL.y + w101*fL.y + w110*hL.y + w111*iL.y;
    r.z = w000*aH.x + w001*bH.x + w010*cH.x + w011*dH.x
        + w100*eH.x + w101*fH.x + w110*hH.x + w111*iH.x;
    r.w = w000*aH.y + w001*bH.y + w010*cH.y + w011*dH.y
        + w100*eH.y + w101*fH.y + w110*hH.y + w111*iH.y;

    __stcs((float4*)(data_out + (size_t)s * CHAN) + sub, r);
}

extern "C" void kernel_launch(void* const* d_in, const int* in_sizes, int n_in,
                              void* d_out, int out_size) {
    const float* rays_o = (const float*)d_in[0];
    const float* rays_d = (const float*)d_in[1];
    const float* data   = (const float*)d_in[2];
    float* out = (float*)d_out;

    const long long MASK_N = (long long)N_RAYS * NSAMP;    // 6,287,360
    const long long INTR_N = (long long)N_RAYS * N_INTERS; // 6,291,456
    long long nm = ((long long)out_size - MASK_N - INTR_N) / 31LL;

    float* data_out = out;
    float* mask_out = out + nm * CHAN;
    float* intr_out = mask_out + MASK_N;
    float* sub_out  = intr_out + INTR_N;

    k_pre<<<TR_BLOCKS + N_RAYS, 256>>>(data, rays_o, rays_d, mask_out, intr_out);
    k_scan<<<1, 1024>>>();
    k_build_map<<<N_RAYS, 256>>>();

    long long nthreads = nm * 8;
    int nblocks = (int)((nthreads + 255) / 256);
    k_gather<<<nblocks, 256>>>(data_out, sub_out, (int)nm);
}

// round 6
// speedup vs baseline: 2.7109x; 1.0139x over previous
#include <cuda_runtime.h>
#include <cuda_fp16.h>
#include <cuda_bf16.h>
#include <stdint.h>

#define N_RAYS   4096
#define N_INTERS 1536
#define NSAMP    1535          // N_INTERS - 1
#define RESV     128
#define CHAN     28
#define NVOX     (128*128*128)
#define CHSTRIDE NVOX
#define TR_BLOCKS (NVOX / 256)   // 8192 transpose blocks

__device__ int    g_ray_count[N_RAYS];
__device__ int    g_ray_base[N_RAYS];
__device__ int    g_map[(size_t)N_RAYS * NSAMP];   // oidx -> (ray<<11)|j
struct RayPack { float4 o_start; float4 d; };
__device__ RayPack g_raypack[N_RAYS];

// channel-last fp16 grid: voxel record = 28 halves + 4 pad = 64B = 4x uint4
__device__ uint4 g_data64[(size_t)NVOX * 4];

// --- mask-critical math: must be bit-stable under --use_fast_math ---
__device__ __forceinline__ float voxel_len() {
    return __fdiv_rn(__fsqrt_rn(27.0f), 1536.0f);
}

__device__ __forceinline__ float compute_start(float ox, float oy, float oz,
                                               float dx, float dy, float dz) {
    float px = __fdiv_rn(1.5f - ox, dx);
    float py = __fdiv_rn(1.5f - oy, dy);
    float pz = __fdiv_rn(1.5f - oz, dz);
    float nx = __fdiv_rn(-1.5f - ox, dx);
    float ny = __fdiv_rn(-1.5f - oy, dy);
    float nz = __fdiv_rn(-1.5f - oz, dz);
    float ix = fminf(px, nx);
    float iy = fminf(py, ny);
    float iz = fminf(pz, nz);
    float s  = fmaxf(fmaxf(ix, iy), iz);
    return fminf(fmaxf(s, 0.2f), 6.0f);
}

__device__ __forceinline__ float sample_t(float start, int j) {
    return __fadd_rn(start, __fmul_rn((float)j, voxel_len()));
}

__device__ __forceinline__ void point_at(float start, int j,
                                         float ox, float oy, float oz,
                                         float dx, float dy, float dz,
                                         float& px, float& py, float& pz) {
    float t = sample_t(start, j);
    px = __fadd_rn(ox, __fmul_rn(t, dx));
    py = __fadd_rn(oy, __fmul_rn(t, dy));
    pz = __fadd_rn(oz, __fmul_rn(t, dz));
}

__device__ __forceinline__ bool in_box(float px, float py, float pz) {
    return (-1.5f < px) & (px < 1.5f) &
           (-1.5f < py) & (py < 1.5f) &
           (-1.5f < pz) & (pz < 1.5f);
}

// unpack 8 halves (uint4) into 8 floats
__device__ __forceinline__ void unpack8(uint4 u, float* f) {
    float2 t;
    t = __half22float2(*reinterpret_cast<__half2*>(&u.x)); f[0]=t.x; f[1]=t.y;
    t = __half22float2(*reinterpret_cast<__half2*>(&u.y)); f[2]=t.x; f[3]=t.y;
    t = __half22float2(*reinterpret_cast<__half2*>(&u.z)); f[4]=t.x; f[5]=t.y;
    t = __half22float2(*reinterpret_cast<__half2*>(&u.w)); f[6]=t.x; f[7]=t.y;
}

// ============ Kernel 0 (fused): transpose->fp16  +  mask/count/intersections ========
__global__ void __launch_bounds__(256)
k_pre(const float* __restrict__ data,
      const float* __restrict__ rays_o, const float* __restrict__ rays_d,
      float* __restrict__ mask_out, float* __restrict__ intr_out) {
    __shared__ float tile[28][257];
    int tid = threadIdx.x;

    if (blockIdx.x < TR_BLOCKS) {
        // -------- transpose path: 256 voxels per block --------
        int v0 = blockIdx.x * 256;
        #pragma unroll
        for (int c = 0; c < 28; c++)
            tile[c][tid] = __ldg(data + (size_t)c * CHSTRIDE + v0 + tid);
        __syncthreads();
        unsigned* out = (unsigned*)g_data64;
        #pragma unroll
        for (int k = 0; k < 14; k++) {
            int l  = k * 256 + tid;      // [0, 3584)
            int v  = l / 14;
            int c2 = l - v * 14;         // half2 pair index, 0..13
            __half2 h = __floats2half2_rn(tile[2*c2][v], tile[2*c2+1][v]);
            out[(size_t)(v0 + v) * 16 + c2] = *reinterpret_cast<unsigned*>(&h);
        }
        return;
    }

    // -------- mask path --------
    int ray = blockIdx.x - TR_BLOCKS;
    float ox = rays_o[ray*3+0], oy = rays_o[ray*3+1], oz = rays_o[ray*3+2];
    float dx = rays_d[ray*3+0], dy = rays_d[ray*3+1], dz = rays_d[ray*3+2];
    float start = compute_start(ox, oy, oz, dx, dy, dz);

    if (tid == 0) {
        RayPack rp;
        rp.o_start = make_float4(ox, oy, oz, start);
        rp.d       = make_float4(dx, dy, dz, 0.0f);
        g_raypack[ray] = rp;
    }

    for (int j = tid; j < N_INTERS; j += 256)
        __stcs(intr_out + (size_t)ray * N_INTERS + j, sample_t(start, j));

    int cnt = 0;
    for (int j = tid; j < NSAMP; j += 256) {
        float px, py, pz;
        point_at(start, j, ox, oy, oz, dx, dy, dz, px, py, pz);
        bool m = in_box(px, py, pz);
        __stcs(mask_out + (size_t)ray * NSAMP + j, m ? 1.0f : 0.0f);
        cnt += m;
    }
    int* sh = (int*)tile;  // reuse smem
    for (int o = 16; o > 0; o >>= 1) cnt += __shfl_down_sync(0xffffffffu, cnt, o);
    if ((tid & 31) == 0) sh[tid >> 5] = cnt;
    __syncthreads();
    if (tid == 0) {
        int s = 0;
        #pragma unroll
        for (int w = 0; w < 8; w++) s += sh[w];
        g_ray_count[ray] = s;
    }
}

// =====================  Kernel 2: exclusive scan over 4096 ray counts ================
__global__ void __launch_bounds__(1024)
k_scan() {
    __shared__ int sh[1024];
    int tid = threadIdx.x;
    int c0 = g_ray_count[tid*4+0];
    int c1 = g_ray_count[tid*4+1];
    int c2 = g_ray_count[tid*4+2];
    int c3 = g_ray_count[tid*4+3];
    int tot = c0 + c1 + c2 + c3;
    sh[tid] = tot;
    __syncthreads();
    for (int off = 1; off < 1024; off <<= 1) {
        int v = (tid >= off) ? sh[tid - off] : 0;
        __syncthreads();
        sh[tid] += v;
        __syncthreads();
    }
    int excl = sh[tid] - tot;
    g_ray_base[tid*4+0] = excl;
    g_ray_base[tid*4+1] = excl + c0;
    g_ray_base[tid*4+2] = excl + c0 + c1;
    g_ray_base[tid*4+3] = excl + c0 + c1 + c2;
}

// =====================  Kernel 2b: build oidx -> (ray, j) map  =======================
__global__ void __launch_bounds__(256)
k_build_map() {
    int ray  = blockIdx.x;
    int cnt  = g_ray_count[ray];
    int base = g_ray_base[ray];
    int tag  = ray << 11;
    for (int j = threadIdx.x; j < cnt; j += 256)
        g_map[base + j] = tag | j;
}

// =====================  Kernel 3: flat gather, 4 lanes per sample, fp16 grid =========
__global__ void __launch_bounds__(256)
k_gather(float* __restrict__ data_out, float* __restrict__ sub_out, int nm) {
    int gt = blockIdx.x * 256 + threadIdx.x;
    int s   = gt >> 2;
    int sub = gt & 3;
    if (s >= nm) return;

    int info = __ldg(&g_map[s]);
    int ray = info >> 11;
    int j   = info & 2047;

    float4 osr = __ldg(&g_raypack[ray].o_start);
    float4 dd  = __ldg(&g_raypack[ray].d);

    float px, py, pz;
    point_at(osr.w, j, osr.x, osr.y, osr.z, dd.x, dd.y, dd.z, px, py, pz);

    const float INV = 0.66666668653f;  // float(2/3)
    float nx = (px + 1.5f) * INV - 1.0f;
    float ny = (py + 1.5f) * INV - 1.0f;
    float nz = (pz + 1.5f) * INV - 1.0f;

    // trilinear coords
    float x = (nx + 1.0f) * 63.5f;
    float y = (ny + 1.0f) * 63.5f;
    float z = (nz + 1.0f) * 63.5f;
    float x0f = floorf(x), y0f = floorf(y), z0f = floorf(z);
    float fx = x - x0f, fy = y - y0f, fz = z - z0f;
    int ix0 = min(max((int)x0f, 0), 127);
    int iy0 = min(max((int)y0f, 0), 127);
    int iz0 = min(max((int)z0f, 0), 127);
    int ix1 = min(ix0 + 1, 127);
    int iy1 = min(iy0 + 1, 127);
    int iz1 = min(iz0 + 1, 127);

    float gxc = 1.0f - fx, gyc = 1.0f - fy, gzc = 1.0f - fz;
    float w000 = gzc * gyc * gxc;
    float w001 = gzc * gyc * fx;
    float w010 = gzc * fy  * gxc;
    float w011 = gzc * fy  * fx;
    float w100 = fz  * gyc * gxc;
    float w101 = fz  * gyc * fx;
    float w110 = fz  * fy  * gxc;
    float w111 = fz  * fy  * fx;

    int b00 = (iz0 * RESV + iy0) * RESV;
    int b01 = (iz0 * RESV + iy1) * RESV;
    int b10 = (iz1 * RESV + iy0) * RESV;
    int b11 = (iz1 * RESV + iy1) * RESV;

    const uint4* G = g_data64;
    uint4 a = __ldg(G + (((size_t)(b00 + ix0)) << 2) + sub);
    uint4 b = __ldg(G + (((size_t)(b00 + ix1)) << 2) + sub);
    uint4 c = __ldg(G + (((size_t)(b01 + ix0)) << 2) + sub);
    uint4 d = __ldg(G + (((size_t)(b01 + ix1)) << 2) + sub);
    uint4 e = __ldg(G + (((size_t)(b10 + ix0)) << 2) + sub);
    uint4 f = __ldg(G + (((size_t)(b10 + ix1)) << 2) + sub);
    uint4 h = __ldg(G + (((size_t)(b11 + ix0)) << 2) + sub);
    uint4 i = __ldg(G + (((size_t)(b11 + ix1)) << 2) + sub);

    float fa[8], fb[8], fc[8], fd[8], fe[8], ff[8], fh[8], fi[8];
    unpack8(a, fa); unpack8(b, fb); unpack8(c, fc); unpack8(d, fd);
    unpack8(e, fe); unpack8(f, ff); unpack8(h, fh); unpack8(i, fi);

    float r[8];
    #pragma unroll
    for (int k = 0; k < 8; k++) {
        r[k] = w000*fa[k] + w001*fb[k] + w010*fc[k] + w011*fd[k]
             + w100*fe[k] + w101*ff[k] + w110*fh[k] + w111*fi[k];
    }

    float4* op = (float4*)(data_out + (size_t)s * CHAN);
    __stcs(op + sub*2, make_float4(r[0], r[1], r[2], r[3]));
    if (sub < 3) {
        __stcs(op + sub*2 + 1, make_float4(r[4], r[5], r[6], r[7]));
    } else {
        // sub == 3: groups 24..27 already stored above; also write sub_pts
        float gx = (nx + 1.0f) * 64.0f;
        float gy = (ny + 1.0f) * 64.0f;
        float gz = (nz + 1.0f) * 64.0f;
        float gix = fminf(fmaxf(floorf(gx), 0.0f), 127.0f);
        float giy = fminf(fmaxf(floorf(gy), 0.0f), 127.0f);
        float giz = fminf(fmaxf(floorf(gz), 0.0f), 127.0f);
        __stcs(sub_out + (size_t)s*3+0, gx - gix);
        __stcs(sub_out + (size_t)s*3+1, gy - giy);
        __stcs(sub_out + (size_t)s*3+2, gz - giz);
    }
}

extern "C" void kernel_launch(void* const* d_in, const int* in_sizes, int n_in,
                              void* d_out, int out_size) {
    const float* rays_o = (const float*)d_in[0];
    const float* rays_d = (const float*)d_in[1];
    const float* data   = (const float*)d_in[2];
    float* out = (float*)d_out;

    const long long MASK_N = (long long)N_RAYS * NSAMP;    // 6,287,360
    const long long INTR_N = (long long)N_RAYS * N_INTERS; // 6,291,456
    long long nm = ((long long)out_size - MASK_N - INTR_N) / 31LL;

    float* data_out = out;
    float* mask_out = out + nm * CHAN;
    float* intr_out = mask_out + MASK_N;
    float* sub_out  = intr_out + INTR_N;

    k_pre<<<TR_BLOCKS + N_RAYS, 256>>>(data, rays_o, rays_d, mask_out, intr_out);
    k_scan<<<1, 1024>>>();
    k_build_map<<<N_RAYS, 256>>>();

    long long nthreads = nm * 4;
    int nblocks = (int)((nthreads + 255) / 256);
    k_gather<<<nblocks, 256>>>(data_out, sub_out, (int)nm);
}